// round 1
// baseline (speedup 1.0000x reference)
#include <cuda_runtime.h>

#define N_NODES 100000
#define IN_DIM 128
#define N_HEADS 4
#define D_HEAD 32
#define N_EDGES 800000
#define LN_EPS 1e-5f
#define NEG_SLOPE 0.2f

#define SCAN_BLOCKS 98   // ceil(100000/1024)

// ---- scratch (static device globals; no allocation allowed) ----
__device__ float4 g_h[N_NODES * 32];     // projected features, [N][128] as float4
__device__ float4 g_ssrc[N_NODES];       // per-node src-half score, 4 heads
__device__ float4 g_sdst[N_NODES];       // per-node dst-half score, 4 heads
__device__ float4 g_expw[N_EDGES];       // exp(leaky(s)) per edge, 4 heads
__device__ int    g_cnt[N_NODES];        // in-degree histogram
__device__ int    g_off[N_NODES];        // CSR row offsets
__device__ int    g_cur[N_NODES];        // scatter cursors
__device__ int    g_eidx[N_EDGES];       // edge ids grouped by dst
__device__ int    g_bsum[128];           // scan partials
__device__ int    g_bpre[128];           // scan partial prefixes

// ---------------------------------------------------------------
__global__ void zero_cnt_kernel() {
    int i = blockIdx.x * blockDim.x + threadIdx.x;
    if (i < N_NODES) g_cnt[i] = 0;
}

// ---------------------------------------------------------------
// Projection: h = x @ W  (tile 64 rows x 128 cols per block iter)
// 256 threads: warp tr owns rows tr*8..tr*8+7; lane tc owns cols 4tc..4tc+3.
// Uses packed fma.rn.f32x2 (2 fp32 FMA per instruction).
// Epilogue: per-node score halves via 8-lane shuffle reduction per head.
__global__ void proj_kernel(const float* __restrict__ x, const float* __restrict__ W,
                            const float* __restrict__ a_src, const float* __restrict__ a_dst)
{
    extern __shared__ char smem[];
    ulonglong2* WsV = (ulonglong2*)smem;            // 128*32 * 16B = 64KB
    float4* xs4 = (float4*)(smem + 65536);          // 64*32 * 16B = 32KB

    int t = threadIdx.x;
    int tc = t & 31;        // col group (lane)
    int tr = t >> 5;        // row group (warp)

    const ulonglong2* Wg = (const ulonglong2*)W;
    for (int i = t; i < 128 * 32; i += 256) WsV[i] = Wg[i];

    float asv[4], adv[4];
#pragma unroll
    for (int i = 0; i < 4; i++) {
        asv[i] = a_src[(tc & 7) * 4 + i];
        adv[i] = a_dst[(tc & 7) * 4 + i];
    }
    int head = tc >> 3;
    __syncthreads();

    const int NTILES = (N_NODES + 63) / 64;
    const float4* xg = (const float4*)x;

    for (int tile = blockIdx.x; tile < NTILES; tile += gridDim.x) {
        int row0 = tile * 64;
        for (int i = t; i < 64 * 32; i += 256) {
            int gr = row0 + (i >> 5);
            xs4[i] = (gr < N_NODES) ? xg[gr * 32 + (i & 31)] : make_float4(0.f, 0.f, 0.f, 0.f);
        }
        __syncthreads();

        unsigned long long acc[8][2];
#pragma unroll
        for (int j = 0; j < 8; j++) { acc[j][0] = 0ull; acc[j][1] = 0ull; }

#pragma unroll 2
        for (int k4 = 0; k4 < 32; k4++) {
            float4 xf[8];
#pragma unroll
            for (int j = 0; j < 8; j++) xf[j] = xs4[(tr * 8 + j) * 32 + k4];
#pragma unroll
            for (int kk = 0; kk < 4; kk++) {
                ulonglong2 w2 = WsV[(k4 * 4 + kk) * 32 + tc];
#pragma unroll
                for (int j = 0; j < 8; j++) {
                    float xv = (kk == 0) ? xf[j].x : (kk == 1) ? xf[j].y : (kk == 2) ? xf[j].z : xf[j].w;
                    unsigned long long x2;
                    asm("mov.b64 %0, {%1, %1};" : "=l"(x2) : "r"(__float_as_uint(xv)));
                    asm("fma.rn.f32x2 %0, %1, %2, %0;" : "+l"(acc[j][0]) : "l"(x2), "l"(w2.x));
                    asm("fma.rn.f32x2 %0, %1, %2, %0;" : "+l"(acc[j][1]) : "l"(x2), "l"(w2.y));
                }
            }
        }

        // epilogue: write h, reduce per-head score halves
#pragma unroll
        for (int j = 0; j < 8; j++) {
            int gr = row0 + tr * 8 + j;
            union { unsigned long long u; float2 f; } c0, c1;
            c0.u = acc[j][0]; c1.u = acc[j][1];
            float f0 = c0.f.x, f1 = c0.f.y, f2 = c1.f.x, f3 = c1.f.y;
            float ps = f0 * asv[0] + f1 * asv[1] + f2 * asv[2] + f3 * asv[3];
            float pd = f0 * adv[0] + f1 * adv[1] + f2 * adv[2] + f3 * adv[3];
#pragma unroll
            for (int o = 4; o; o >>= 1) {
                ps += __shfl_xor_sync(0xffffffffu, ps, o, 8);
                pd += __shfl_xor_sync(0xffffffffu, pd, o, 8);
            }
            if (gr < N_NODES) {
                g_h[gr * 32 + tc] = make_float4(f0, f1, f2, f3);
                if ((tc & 7) == 0) {
                    ((float*)g_ssrc)[gr * 4 + head] = ps;
                    ((float*)g_sdst)[gr * 4 + head] = pd;
                }
            }
        }
        __syncthreads();
    }
}

// ---------------------------------------------------------------
// Per-edge: s = ssrc[src] + sdst[dst]; leaky; exp; histogram of dst.
__global__ void edge_kernel(const int* __restrict__ src, const int* __restrict__ dst) {
    int e = blockIdx.x * blockDim.x + threadIdx.x;
    if (e >= N_EDGES) return;
    int s = src[e], d = dst[e];
    float4 a = g_ssrc[s];
    float4 b = g_sdst[d];
    float v0 = a.x + b.x, v1 = a.y + b.y, v2 = a.z + b.z, v3 = a.w + b.w;
    v0 = (v0 > 0.f) ? v0 : NEG_SLOPE * v0;
    v1 = (v1 > 0.f) ? v1 : NEG_SLOPE * v1;
    v2 = (v2 > 0.f) ? v2 : NEG_SLOPE * v2;
    v3 = (v3 > 0.f) ? v3 : NEG_SLOPE * v3;
    g_expw[e] = make_float4(__expf(v0), __expf(v1), __expf(v2), __expf(v3));
    atomicAdd(&g_cnt[d], 1);
}

// ---------------------------------------------------------------
__device__ __forceinline__ int block_scan_inclusive(int v, int t, int* total) {
    __shared__ int wsum[32];
    int lane = t & 31, wid = t >> 5;
    int x = v;
#pragma unroll
    for (int o = 1; o < 32; o <<= 1) {
        int y = __shfl_up_sync(0xffffffffu, x, o);
        if (lane >= o) x += y;
    }
    if (lane == 31) wsum[wid] = x;
    __syncthreads();
    int nw = blockDim.x >> 5;
    if (t < 32) {
        int s = (t < nw) ? wsum[t] : 0;
#pragma unroll
        for (int o = 1; o < 32; o <<= 1) {
            int y = __shfl_up_sync(0xffffffffu, s, o);
            if (t >= o) s += y;
        }
        wsum[t] = s;
    }
    __syncthreads();
    int pre = (wid > 0) ? wsum[wid - 1] : 0;
    *total = wsum[nw - 1];
    return x + pre;
}

__global__ void scan_part1() {
    int b = blockIdx.x, t = threadIdx.x;
    int i = b * 1024 + t;
    int v = (i < N_NODES) ? g_cnt[i] : 0;
    int total;
    block_scan_inclusive(v, t, &total);
    if (t == 0) g_bsum[b] = total;
}

__global__ void scan_part2() {
    int t = threadIdx.x;  // 128 threads
    int v = (t < SCAN_BLOCKS) ? g_bsum[t] : 0;
    int total;
    int incl = block_scan_inclusive(v, t, &total);
    if (t < SCAN_BLOCKS) g_bpre[t] = incl - v;
}

__global__ void scan_part3() {
    int b = blockIdx.x, t = threadIdx.x;
    int i = b * 1024 + t;
    int v = (i < N_NODES) ? g_cnt[i] : 0;
    int total;
    int incl = block_scan_inclusive(v, t, &total);
    if (i < N_NODES) {
        int o = g_bpre[b] + incl - v;
        g_off[i] = o;
        g_cur[i] = o;
    }
}

// ---------------------------------------------------------------
__global__ void scatter_kernel(const int* __restrict__ dst) {
    int e = blockIdx.x * blockDim.x + threadIdx.x;
    if (e >= N_EDGES) return;
    int d = dst[e];
    int pos = atomicAdd(&g_cur[d], 1);
    g_eidx[pos] = e;
}

// ---------------------------------------------------------------
// Warp per dst node: softmax-weighted aggregation + residual + LN + ELU.
__global__ void agg_kernel(const float* __restrict__ x, const int* __restrict__ src,
                           const float* __restrict__ gamma, const float* __restrict__ beta,
                           float* __restrict__ out)
{
    int w = (blockIdx.x * blockDim.x + threadIdx.x) >> 5;
    int lane = threadIdx.x & 31;
    if (w >= N_NODES) return;

    int start = g_off[w];
    int deg = g_cnt[w];
    int head = lane >> 3;

    float4 acc = make_float4(0.f, 0.f, 0.f, 0.f);
    float dsum = 0.f;
    for (int i = 0; i < deg; i++) {
        int e = g_eidx[start + i];
        int s = src[e];
        float4 ew = g_expw[e];
        float wgt = (head == 0) ? ew.x : (head == 1) ? ew.y : (head == 2) ? ew.z : ew.w;
        float4 hv = g_h[s * 32 + lane];
        acc.x += hv.x * wgt; acc.y += hv.y * wgt; acc.z += hv.z * wgt; acc.w += hv.w * wgt;
        dsum += wgt;
    }
    float inv = (deg > 0) ? (1.f / dsum) : 0.f;

    const float4* x4 = (const float4*)x;
    float4 xv = x4[w * 32 + lane];
    float r0 = acc.x * inv + xv.x;
    float r1 = acc.y * inv + xv.y;
    float r2 = acc.z * inv + xv.z;
    float r3 = acc.w * inv + xv.w;

    // LayerNorm over 128 (32 lanes x 4)
    float s1 = r0 + r1 + r2 + r3;
#pragma unroll
    for (int o = 16; o; o >>= 1) s1 += __shfl_xor_sync(0xffffffffu, s1, o);
    float mean = s1 * (1.0f / 128.0f);
    float d0 = r0 - mean, d1 = r1 - mean, d2 = r2 - mean, d3 = r3 - mean;
    float s2 = d0 * d0 + d1 * d1 + d2 * d2 + d3 * d3;
#pragma unroll
    for (int o = 16; o; o >>= 1) s2 += __shfl_xor_sync(0xffffffffu, s2, o);
    float rstd = rsqrtf(s2 * (1.0f / 128.0f) + LN_EPS);

    float4 g = ((const float4*)gamma)[lane];
    float4 bb = ((const float4*)beta)[lane];
    float o0 = d0 * rstd * g.x + bb.x;
    float o1 = d1 * rstd * g.y + bb.y;
    float o2 = d2 * rstd * g.z + bb.z;
    float o3 = d3 * rstd * g.w + bb.w;
    // ELU
    o0 = (o0 > 0.f) ? o0 : expm1f(o0);
    o1 = (o1 > 0.f) ? o1 : expm1f(o1);
    o2 = (o2 > 0.f) ? o2 : expm1f(o2);
    o3 = (o3 > 0.f) ? o3 : expm1f(o3);

    ((float4*)out)[w * 32 + lane] = make_float4(o0, o1, o2, o3);
}

// ---------------------------------------------------------------
extern "C" void kernel_launch(void* const* d_in, const int* in_sizes, int n_in,
                              void* d_out, int out_size)
{
    const float* x      = (const float*)d_in[0];
    const int*   ei     = (const int*)d_in[1];
    const float* W      = (const float*)d_in[2];
    const float* a_src  = (const float*)d_in[3];
    const float* a_dst  = (const float*)d_in[4];
    const float* gamma  = (const float*)d_in[5];
    const float* beta   = (const float*)d_in[6];
    float* out = (float*)d_out;

    const int* src = ei;
    const int* dst = ei + N_EDGES;

    cudaFuncSetAttribute(proj_kernel, cudaFuncAttributeMaxDynamicSharedMemorySize, 98304);

    zero_cnt_kernel<<<(N_NODES + 255) / 256, 256>>>();
    proj_kernel<<<296, 256, 98304>>>(x, W, a_src, a_dst);
    edge_kernel<<<(N_EDGES + 255) / 256, 256>>>(src, dst);
    scan_part1<<<SCAN_BLOCKS, 1024>>>();
    scan_part2<<<1, 128>>>();
    scan_part3<<<SCAN_BLOCKS, 1024>>>();
    scatter_kernel<<<(N_EDGES + 255) / 256, 256>>>(dst);
    agg_kernel<<<(N_NODES * 32 + 255) / 256, 256>>>(x, src, gamma, beta, out);
}

// round 2
// speedup vs baseline: 1.0900x; 1.0900x over previous
#include <cuda_runtime.h>

#define N_NODES 100000
#define IN_DIM 128
#define N_HEADS 4
#define D_HEAD 32
#define N_EDGES 800000
#define LN_EPS 1e-5f
#define NEG_SLOPE 0.2f

#define SCAN_BLOCKS 98   // ceil(100000/1024)

// ---- scratch (static device globals; no allocation allowed) ----
__device__ float4 g_h[N_NODES * 32];     // projected features, [N][128] as float4
__device__ float4 g_ssrc[N_NODES];       // per-node src-half score, 4 heads
__device__ float4 g_sdst[N_NODES];       // per-node dst-half score, 4 heads
__device__ float4 g_expws[N_EDGES];      // exp weights, CSR-sorted by dst
__device__ int    g_srcs[N_EDGES];       // src ids, CSR-sorted by dst
__device__ int    g_cnt[N_NODES];        // in-degree histogram
__device__ int    g_off[N_NODES];        // CSR row offsets
__device__ int    g_cur[N_NODES];        // scatter cursors
__device__ int    g_bsum[SCAN_BLOCKS];   // scan partials
__device__ int    g_flag;                // scan arrival counter

// ---------------------------------------------------------------
// Projection: h = x @ W  (tile 64 rows x 128 cols per block iter)
// Uses packed fma.rn.f32x2 (2 fp32 FMA per instruction).
// Epilogue: per-node score halves via 8-lane shuffle reduction per head.
__global__ void proj_kernel(const float* __restrict__ x, const float* __restrict__ W,
                            const float* __restrict__ a_src, const float* __restrict__ a_dst)
{
    extern __shared__ char smem[];
    ulonglong2* WsV = (ulonglong2*)smem;            // 128*32 * 16B = 64KB
    float4* xs4 = (float4*)(smem + 65536);          // 64*32 * 16B = 32KB

    int t = threadIdx.x;
    int tc = t & 31;        // col group (lane)
    int tr = t >> 5;        // row group (warp)

    const ulonglong2* Wg = (const ulonglong2*)W;
    for (int i = t; i < 128 * 32; i += 256) WsV[i] = Wg[i];

    float asv[4], adv[4];
#pragma unroll
    for (int i = 0; i < 4; i++) {
        asv[i] = a_src[(tc & 7) * 4 + i];
        adv[i] = a_dst[(tc & 7) * 4 + i];
    }
    int head = tc >> 3;
    __syncthreads();

    const int NTILES = (N_NODES + 63) / 64;
    const float4* xg = (const float4*)x;

    for (int tile = blockIdx.x; tile < NTILES; tile += gridDim.x) {
        int row0 = tile * 64;
        for (int i = t; i < 64 * 32; i += 256) {
            int gr = row0 + (i >> 5);
            xs4[i] = (gr < N_NODES) ? xg[gr * 32 + (i & 31)] : make_float4(0.f, 0.f, 0.f, 0.f);
        }
        __syncthreads();

        unsigned long long acc[8][2];
#pragma unroll
        for (int j = 0; j < 8; j++) { acc[j][0] = 0ull; acc[j][1] = 0ull; }

#pragma unroll 2
        for (int k4 = 0; k4 < 32; k4++) {
            float4 xf[8];
#pragma unroll
            for (int j = 0; j < 8; j++) xf[j] = xs4[(tr * 8 + j) * 32 + k4];
#pragma unroll
            for (int kk = 0; kk < 4; kk++) {
                ulonglong2 w2 = WsV[(k4 * 4 + kk) * 32 + tc];
#pragma unroll
                for (int j = 0; j < 8; j++) {
                    float xv = (kk == 0) ? xf[j].x : (kk == 1) ? xf[j].y : (kk == 2) ? xf[j].z : xf[j].w;
                    unsigned long long x2;
                    asm("mov.b64 %0, {%1, %1};" : "=l"(x2) : "r"(__float_as_uint(xv)));
                    asm("fma.rn.f32x2 %0, %1, %2, %0;" : "+l"(acc[j][0]) : "l"(x2), "l"(w2.x));
                    asm("fma.rn.f32x2 %0, %1, %2, %0;" : "+l"(acc[j][1]) : "l"(x2), "l"(w2.y));
                }
            }
        }

        // epilogue: write h, reduce per-head score halves
#pragma unroll
        for (int j = 0; j < 8; j++) {
            int gr = row0 + tr * 8 + j;
            union { unsigned long long u; float2 f; } c0, c1;
            c0.u = acc[j][0]; c1.u = acc[j][1];
            float f0 = c0.f.x, f1 = c0.f.y, f2 = c1.f.x, f3 = c1.f.y;
            float ps = f0 * asv[0] + f1 * asv[1] + f2 * asv[2] + f3 * asv[3];
            float pd = f0 * adv[0] + f1 * adv[1] + f2 * adv[2] + f3 * adv[3];
#pragma unroll
            for (int o = 4; o; o >>= 1) {
                ps += __shfl_xor_sync(0xffffffffu, ps, o, 8);
                pd += __shfl_xor_sync(0xffffffffu, pd, o, 8);
            }
            if (gr < N_NODES) {
                g_h[gr * 32 + tc] = make_float4(f0, f1, f2, f3);
                if ((tc & 7) == 0) {
                    ((float*)g_ssrc)[gr * 4 + head] = ps;
                    ((float*)g_sdst)[gr * 4 + head] = pd;
                }
            }
        }
        __syncthreads();
    }
}

// ---------------------------------------------------------------
// Histogram of dst; also resets the scan flag for this replay.
__global__ void hist_kernel(const int* __restrict__ dst) {
    if (blockIdx.x == 0 && threadIdx.x == 0) g_flag = 0;
    int e = blockIdx.x * blockDim.x + threadIdx.x;
    if (e >= N_EDGES) return;
    atomicAdd(&g_cnt[dst[e]], 1);
}

// ---------------------------------------------------------------
__device__ __forceinline__ int block_scan_inclusive(int v, int t, int* total) {
    __shared__ int wsum[32];
    int lane = t & 31, wid = t >> 5;
    int x = v;
#pragma unroll
    for (int o = 1; o < 32; o <<= 1) {
        int y = __shfl_up_sync(0xffffffffu, x, o);
        if (lane >= o) x += y;
    }
    if (lane == 31) wsum[wid] = x;
    __syncthreads();
    int nw = blockDim.x >> 5;
    if (t < 32) {
        int s = (t < nw) ? wsum[t] : 0;
#pragma unroll
        for (int o = 1; o < 32; o <<= 1) {
            int y = __shfl_up_sync(0xffffffffu, s, o);
            if (t >= o) s += y;
        }
        wsum[t] = s;
    }
    __syncthreads();
    int pre = (wid > 0) ? wsum[wid - 1] : 0;
    *total = wsum[nw - 1];
    return x + pre;
}

// Single-wave fused scan: 98 blocks are guaranteed co-resident (< 148 SMs).
__global__ void scan_all_kernel() {
    __shared__ int sb[SCAN_BLOCKS];
    int b = blockIdx.x, t = threadIdx.x;
    int i = b * 1024 + t;
    int v = (i < N_NODES) ? g_cnt[i] : 0;
    int total;
    int incl = block_scan_inclusive(v, t, &total);
    if (t == 0) {
        g_bsum[b] = total;
        __threadfence();
        atomicAdd(&g_flag, 1);
        while (((volatile int*)&g_flag)[0] < SCAN_BLOCKS) { }
    }
    __syncthreads();
    if (t < SCAN_BLOCKS) sb[t] = ((volatile int*)g_bsum)[t];
    __syncthreads();
    int pre = 0;
    for (int j = 0; j < b; j++) pre += sb[j];
    if (i < N_NODES) {
        int o = pre + incl - v;
        g_off[i] = o;
        g_cur[i] = o;
    }
}

// ---------------------------------------------------------------
// Per-edge: score, leaky, exp; claim slot in dst's CSR segment; write
// payloads (src id + exp weights) already sorted by dst.
__global__ void edge_scatter_kernel(const int* __restrict__ src, const int* __restrict__ dst) {
    int e = blockIdx.x * blockDim.x + threadIdx.x;
    if (e >= N_EDGES) return;
    int s = src[e], d = dst[e];
    float4 a = g_ssrc[s];
    float4 b = g_sdst[d];
    float v0 = a.x + b.x, v1 = a.y + b.y, v2 = a.z + b.z, v3 = a.w + b.w;
    v0 = (v0 > 0.f) ? v0 : NEG_SLOPE * v0;
    v1 = (v1 > 0.f) ? v1 : NEG_SLOPE * v1;
    v2 = (v2 > 0.f) ? v2 : NEG_SLOPE * v2;
    v3 = (v3 > 0.f) ? v3 : NEG_SLOPE * v3;
    int pos = atomicAdd(&g_cur[d], 1);
    g_srcs[pos] = s;
    g_expws[pos] = make_float4(__expf(v0), __expf(v1), __expf(v2), __expf(v3));
}

// ---------------------------------------------------------------
// Warp per dst node: softmax-weighted aggregation + residual + LN + ELU.
// src id and weights are uniform (broadcast) loads; only h is a true gather.
__global__ void agg_kernel(const float* __restrict__ x,
                           const float* __restrict__ gamma, const float* __restrict__ beta,
                           float* __restrict__ out)
{
    int w = (blockIdx.x * blockDim.x + threadIdx.x) >> 5;
    int lane = threadIdx.x & 31;
    if (w >= N_NODES) return;

    int start = g_off[w];
    int deg = g_cnt[w];
    int head = lane >> 3;

    float4 acc = make_float4(0.f, 0.f, 0.f, 0.f);
    float dsum = 0.f;
#pragma unroll 4
    for (int i = 0; i < deg; i++) {
        int s = __ldg(&g_srcs[start + i]);             // uniform broadcast
        float4 ew = g_expws[start + i];                // uniform broadcast
        float wgt = (head == 0) ? ew.x : (head == 1) ? ew.y : (head == 2) ? ew.z : ew.w;
        float4 hv = g_h[s * 32 + lane];                // coalesced 128B gather
        acc.x += hv.x * wgt; acc.y += hv.y * wgt; acc.z += hv.z * wgt; acc.w += hv.w * wgt;
        dsum += wgt;
    }
    float inv = (deg > 0) ? (1.f / dsum) : 0.f;

    const float4* x4 = (const float4*)x;
    float4 xv = x4[w * 32 + lane];
    float r0 = acc.x * inv + xv.x;
    float r1 = acc.y * inv + xv.y;
    float r2 = acc.z * inv + xv.z;
    float r3 = acc.w * inv + xv.w;

    // LayerNorm over 128 (32 lanes x 4)
    float s1 = r0 + r1 + r2 + r3;
#pragma unroll
    for (int o = 16; o; o >>= 1) s1 += __shfl_xor_sync(0xffffffffu, s1, o);
    float mean = s1 * (1.0f / 128.0f);
    float d0 = r0 - mean, d1 = r1 - mean, d2 = r2 - mean, d3 = r3 - mean;
    float s2 = d0 * d0 + d1 * d1 + d2 * d2 + d3 * d3;
#pragma unroll
    for (int o = 16; o; o >>= 1) s2 += __shfl_xor_sync(0xffffffffu, s2, o);
    float rstd = rsqrtf(s2 * (1.0f / 128.0f) + LN_EPS);

    float4 g = ((const float4*)gamma)[lane];
    float4 bb = ((const float4*)beta)[lane];
    float o0 = d0 * rstd * g.x + bb.x;
    float o1 = d1 * rstd * g.y + bb.y;
    float o2 = d2 * rstd * g.z + bb.z;
    float o3 = d3 * rstd * g.w + bb.w;
    // ELU
    o0 = (o0 > 0.f) ? o0 : expm1f(o0);
    o1 = (o1 > 0.f) ? o1 : expm1f(o1);
    o2 = (o2 > 0.f) ? o2 : expm1f(o2);
    o3 = (o3 > 0.f) ? o3 : expm1f(o3);

    ((float4*)out)[w * 32 + lane] = make_float4(o0, o1, o2, o3);
}

// ---------------------------------------------------------------
extern "C" void kernel_launch(void* const* d_in, const int* in_sizes, int n_in,
                              void* d_out, int out_size)
{
    const float* x      = (const float*)d_in[0];
    const int*   ei     = (const int*)d_in[1];
    const float* W      = (const float*)d_in[2];
    const float* a_src  = (const float*)d_in[3];
    const float* a_dst  = (const float*)d_in[4];
    const float* gamma  = (const float*)d_in[5];
    const float* beta   = (const float*)d_in[6];
    float* out = (float*)d_out;

    const int* src = ei;
    const int* dst = ei + N_EDGES;

    cudaFuncSetAttribute(proj_kernel, cudaFuncAttributeMaxDynamicSharedMemorySize, 98304);

    void* cnt_addr = nullptr;
    cudaGetSymbolAddress(&cnt_addr, g_cnt);
    cudaMemsetAsync(cnt_addr, 0, N_NODES * sizeof(int), 0);

    hist_kernel<<<(N_EDGES + 255) / 256, 256>>>(dst);
    scan_all_kernel<<<SCAN_BLOCKS, 1024>>>();
    proj_kernel<<<296, 256, 98304>>>(x, W, a_src, a_dst);
    edge_scatter_kernel<<<(N_EDGES + 255) / 256, 256>>>(src, dst);
    agg_kernel<<<(N_NODES * 32 + 255) / 256, 256>>>(x, gamma, beta, out);
}

// round 5
// speedup vs baseline: 1.1391x; 1.0450x over previous
#include <cuda_runtime.h>

#define N_NODES 100000
#define IN_DIM 128
#define N_HEADS 4
#define D_HEAD 32
#define N_EDGES 800000
#define LN_EPS 1e-5f
#define NEG_SLOPE 0.2f

#define SCAN_BLOCKS 98   // ceil(100000/1024)

// ---- scratch (static device globals; no allocation allowed) ----
__device__ float4 g_h[N_NODES * 32];     // projected features, [N][128] as float4
__device__ float4 g_ssrc[N_NODES];       // per-node src-half score, 4 heads
__device__ float4 g_sdst[N_NODES];       // per-node dst-half score, 4 heads
__device__ int    g_srcs[N_EDGES];       // src ids, CSR-sorted by dst
__device__ int    g_cnt[N_NODES];        // in-degree histogram
__device__ int    g_off[N_NODES];        // CSR row offsets
__device__ int    g_cur[N_NODES];        // scatter cursors
__device__ int    g_bsum[SCAN_BLOCKS];   // scan partials
__device__ int    g_flag;                // scan arrival counter

// ---------------------------------------------------------------
// Projection: h = x @ W  (tile 64 rows x 128 cols per block iter)
// Packed fma.rn.f32x2 (2 fp32 FMA per instruction).
__global__ void proj_kernel(const float* __restrict__ x, const float* __restrict__ W,
                            const float* __restrict__ a_src, const float* __restrict__ a_dst)
{
    extern __shared__ char smem[];
    ulonglong2* WsV = (ulonglong2*)smem;            // 64KB
    float4* xs4 = (float4*)(smem + 65536);          // 32KB

    int t = threadIdx.x;
    int tc = t & 31;
    int tr = t >> 5;

    const ulonglong2* Wg = (const ulonglong2*)W;
    for (int i = t; i < 128 * 32; i += 256) WsV[i] = Wg[i];

    float asv[4], adv[4];
#pragma unroll
    for (int i = 0; i < 4; i++) {
        asv[i] = a_src[(tc & 7) * 4 + i];
        adv[i] = a_dst[(tc & 7) * 4 + i];
    }
    int head = tc >> 3;
    __syncthreads();

    const int NTILES = (N_NODES + 63) / 64;
    const float4* xg = (const float4*)x;

    for (int tile = blockIdx.x; tile < NTILES; tile += gridDim.x) {
        int row0 = tile * 64;
        for (int i = t; i < 64 * 32; i += 256) {
            int gr = row0 + (i >> 5);
            xs4[i] = (gr < N_NODES) ? xg[gr * 32 + (i & 31)] : make_float4(0.f, 0.f, 0.f, 0.f);
        }
        __syncthreads();

        unsigned long long acc[8][2];
#pragma unroll
        for (int j = 0; j < 8; j++) { acc[j][0] = 0ull; acc[j][1] = 0ull; }

#pragma unroll 2
        for (int k4 = 0; k4 < 32; k4++) {
            float4 xf[8];
#pragma unroll
            for (int j = 0; j < 8; j++) xf[j] = xs4[(tr * 8 + j) * 32 + k4];
#pragma unroll
            for (int kk = 0; kk < 4; kk++) {
                ulonglong2 w2 = WsV[(k4 * 4 + kk) * 32 + tc];
#pragma unroll
                for (int j = 0; j < 8; j++) {
                    float xv = (kk == 0) ? xf[j].x : (kk == 1) ? xf[j].y : (kk == 2) ? xf[j].z : xf[j].w;
                    unsigned long long x2;
                    asm("mov.b64 %0, {%1, %1};" : "=l"(x2) : "r"(__float_as_uint(xv)));
                    asm("fma.rn.f32x2 %0, %1, %2, %0;" : "+l"(acc[j][0]) : "l"(x2), "l"(w2.x));
                    asm("fma.rn.f32x2 %0, %1, %2, %0;" : "+l"(acc[j][1]) : "l"(x2), "l"(w2.y));
                }
            }
        }

#pragma unroll
        for (int j = 0; j < 8; j++) {
            int gr = row0 + tr * 8 + j;
            union { unsigned long long u; float2 f; } c0, c1;
            c0.u = acc[j][0]; c1.u = acc[j][1];
            float f0 = c0.f.x, f1 = c0.f.y, f2 = c1.f.x, f3 = c1.f.y;
            float ps = f0 * asv[0] + f1 * asv[1] + f2 * asv[2] + f3 * asv[3];
            float pd = f0 * adv[0] + f1 * adv[1] + f2 * adv[2] + f3 * adv[3];
#pragma unroll
            for (int o = 4; o; o >>= 1) {
                ps += __shfl_xor_sync(0xffffffffu, ps, o, 8);
                pd += __shfl_xor_sync(0xffffffffu, pd, o, 8);
            }
            if (gr < N_NODES) {
                g_h[gr * 32 + tc] = make_float4(f0, f1, f2, f3);
                if ((tc & 7) == 0) {
                    ((float*)g_ssrc)[gr * 4 + head] = ps;
                    ((float*)g_sdst)[gr * 4 + head] = pd;
                }
            }
        }
        __syncthreads();
    }
}

// ---------------------------------------------------------------
// Histogram of dst (int4-vectorized); resets the scan flag.
__global__ void hist_kernel(const int4* __restrict__ dst4) {
    if (blockIdx.x == 0 && threadIdx.x == 0) g_flag = 0;
    int i = blockIdx.x * blockDim.x + threadIdx.x;
    if (i >= N_EDGES / 4) return;
    int4 d = dst4[i];
    atomicAdd(&g_cnt[d.x], 1);
    atomicAdd(&g_cnt[d.y], 1);
    atomicAdd(&g_cnt[d.z], 1);
    atomicAdd(&g_cnt[d.w], 1);
}

// ---------------------------------------------------------------
__device__ __forceinline__ int block_scan_inclusive(int v, int t, int* total) {
    __shared__ int wsum[32];
    int lane = t & 31, wid = t >> 5;
    int x = v;
#pragma unroll
    for (int o = 1; o < 32; o <<= 1) {
        int y = __shfl_up_sync(0xffffffffu, x, o);
        if (lane >= o) x += y;
    }
    if (lane == 31) wsum[wid] = x;
    __syncthreads();
    int nw = blockDim.x >> 5;
    if (t < 32) {
        int s = (t < nw) ? wsum[t] : 0;
#pragma unroll
        for (int o = 1; o < 32; o <<= 1) {
            int y = __shfl_up_sync(0xffffffffu, s, o);
            if (t >= o) s += y;
        }
        wsum[t] = s;
    }
    __syncthreads();
    int pre = (wid > 0) ? wsum[wid - 1] : 0;
    *total = wsum[nw - 1];
    return x + pre;
}

// Single-wave fused scan (98 blocks < 148 SMs, co-resident).
__global__ void scan_all_kernel() {
    __shared__ int sb[SCAN_BLOCKS];
    int b = blockIdx.x, t = threadIdx.x;
    int i = b * 1024 + t;
    int v = (i < N_NODES) ? g_cnt[i] : 0;
    int total;
    int incl = block_scan_inclusive(v, t, &total);
    if (t == 0) {
        g_bsum[b] = total;
        __threadfence();
        atomicAdd(&g_flag, 1);
        while (((volatile int*)&g_flag)[0] < SCAN_BLOCKS) { }
    }
    __syncthreads();
    if (t < SCAN_BLOCKS) sb[t] = ((volatile int*)g_bsum)[t];
    __syncthreads();
    int pre = 0;
    for (int j = 0; j < b; j++) pre += sb[j];
    if (i < N_NODES) {
        int o = pre + incl - v;
        g_off[i] = o;
        g_cur[i] = o;
    }
}

// ---------------------------------------------------------------
// Scatter ONLY the src id into the dst-grouped CSR (int4-vectorized).
__global__ void scatter_kernel(const int4* __restrict__ src4, const int4* __restrict__ dst4) {
    int i = blockIdx.x * blockDim.x + threadIdx.x;
    if (i >= N_EDGES / 4) return;
    int4 s = src4[i];
    int4 d = dst4[i];
    int p0 = atomicAdd(&g_cur[d.x], 1); g_srcs[p0] = s.x;
    int p1 = atomicAdd(&g_cur[d.y], 1); g_srcs[p1] = s.y;
    int p2 = atomicAdd(&g_cur[d.z], 1); g_srcs[p2] = s.z;
    int p3 = atomicAdd(&g_cur[d.w], 1); g_srcs[p3] = s.w;
}

// ---------------------------------------------------------------
__device__ __forceinline__ float expleaky(float v) {
    v = (v > 0.f) ? v : NEG_SLOPE * v;
    return __expf(v);
}

// Warp per dst node: recompute scores, softmax-weighted aggregation,
// residual + LN + ELU. Src ids loaded coalesced (32/load) + shuffled.
__global__ void agg_kernel(const float* __restrict__ x,
                           const float* __restrict__ gamma, const float* __restrict__ beta,
                           float* __restrict__ out)
{
    int w = (blockIdx.x * blockDim.x + threadIdx.x) >> 5;
    int lane = threadIdx.x & 31;
    if (w >= N_NODES) return;

    int start = g_off[w];
    int deg = g_cnt[w];
    int head = lane >> 3;

    const float* ssrc_f = (const float*)g_ssrc;
    float sdst_h = ((const float*)g_sdst)[w * 4 + head];

    float4 acc = make_float4(0.f, 0.f, 0.f, 0.f);
    float dsum = 0.f;

    for (int chunk = 0; chunk < deg; chunk += 32) {
        int n = deg - chunk; if (n > 32) n = 32;
        int myid = 0;
        if (lane < n) myid = g_srcs[start + chunk + lane];   // coalesced

        int i = 0;
#pragma unroll 1
        for (; i + 4 <= n; i += 4) {
            int s0 = __shfl_sync(0xffffffffu, myid, i);
            int s1 = __shfl_sync(0xffffffffu, myid, i + 1);
            int s2 = __shfl_sync(0xffffffffu, myid, i + 2);
            int s3 = __shfl_sync(0xffffffffu, myid, i + 3);
            float4 h0 = g_h[s0 * 32 + lane];
            float4 h1 = g_h[s1 * 32 + lane];
            float4 h2 = g_h[s2 * 32 + lane];
            float4 h3 = g_h[s3 * 32 + lane];
            float w0 = expleaky(ssrc_f[s0 * 4 + head] + sdst_h);
            float w1 = expleaky(ssrc_f[s1 * 4 + head] + sdst_h);
            float w2 = expleaky(ssrc_f[s2 * 4 + head] + sdst_h);
            float w3 = expleaky(ssrc_f[s3 * 4 + head] + sdst_h);
            acc.x += h0.x * w0 + h1.x * w1 + h2.x * w2 + h3.x * w3;
            acc.y += h0.y * w0 + h1.y * w1 + h2.y * w2 + h3.y * w3;
            acc.z += h0.z * w0 + h1.z * w1 + h2.z * w2 + h3.z * w3;
            acc.w += h0.w * w0 + h1.w * w1 + h2.w * w2 + h3.w * w3;
            dsum += w0 + w1 + w2 + w3;
        }
#pragma unroll 1
        for (; i < n; i++) {
            int s0 = __shfl_sync(0xffffffffu, myid, i);
            float4 h0 = g_h[s0 * 32 + lane];
            float w0 = expleaky(ssrc_f[s0 * 4 + head] + sdst_h);
            acc.x += h0.x * w0; acc.y += h0.y * w0; acc.z += h0.z * w0; acc.w += h0.w * w0;
            dsum += w0;
        }
    }
    float inv = (deg > 0) ? (1.f / dsum) : 0.f;

    const float4* x4 = (const float4*)x;
    float4 xv = x4[w * 32 + lane];
    float r0 = acc.x * inv + xv.x;
    float r1 = acc.y * inv + xv.y;
    float r2 = acc.z * inv + xv.z;
    float r3 = acc.w * inv + xv.w;

    // LayerNorm over 128 (32 lanes x 4)
    float s1 = r0 + r1 + r2 + r3;
#pragma unroll
    for (int o = 16; o; o >>= 1) s1 += __shfl_xor_sync(0xffffffffu, s1, o);
    float mean = s1 * (1.0f / 128.0f);
    float d0 = r0 - mean, d1 = r1 - mean, d2 = r2 - mean, d3 = r3 - mean;
    float s2 = d0 * d0 + d1 * d1 + d2 * d2 + d3 * d3;
#pragma unroll
    for (int o = 16; o; o >>= 1) s2 += __shfl_xor_sync(0xffffffffu, s2, o);
    float rstd = rsqrtf(s2 * (1.0f / 128.0f) + LN_EPS);

    float4 g = ((const float4*)gamma)[lane];
    float4 bb = ((const float4*)beta)[lane];
    float o0 = d0 * rstd * g.x + bb.x;
    float o1 = d1 * rstd * g.y + bb.y;
    float o2 = d2 * rstd * g.z + bb.z;
    float o3 = d3 * rstd * g.w + bb.w;
    o0 = (o0 > 0.f) ? o0 : expm1f(o0);
    o1 = (o1 > 0.f) ? o1 : expm1f(o1);
    o2 = (o2 > 0.f) ? o2 : expm1f(o2);
    o3 = (o3 > 0.f) ? o3 : expm1f(o3);

    ((float4*)out)[w * 32 + lane] = make_float4(o0, o1, o2, o3);
}

// ---------------------------------------------------------------
extern "C" void kernel_launch(void* const* d_in, const int* in_sizes, int n_in,
                              void* d_out, int out_size)
{
    const float* x      = (const float*)d_in[0];
    const int*   ei     = (const int*)d_in[1];
    const float* W      = (const float*)d_in[2];
    const float* a_src  = (const float*)d_in[3];
    const float* a_dst  = (const float*)d_in[4];
    const float* gamma  = (const float*)d_in[5];
    const float* beta   = (const float*)d_in[6];
    float* out = (float*)d_out;

    const int4* src4 = (const int4*)ei;
    const int4* dst4 = (const int4*)(ei + N_EDGES);

    cudaFuncSetAttribute(proj_kernel, cudaFuncAttributeMaxDynamicSharedMemorySize, 98304);

    void* cnt_addr = nullptr;
    cudaGetSymbolAddress(&cnt_addr, g_cnt);
    cudaMemsetAsync(cnt_addr, 0, N_NODES * sizeof(int), 0);

    hist_kernel<<<(N_EDGES / 4 + 255) / 256, 256>>>(dst4);
    scan_all_kernel<<<SCAN_BLOCKS, 1024>>>();
    scatter_kernel<<<(N_EDGES / 4 + 255) / 256, 256>>>(src4, dst4);
    proj_kernel<<<296, 256, 98304>>>(x, W, a_src, a_dst);
    agg_kernel<<<(N_NODES * 32 + 255) / 256, 256>>>(x, gamma, beta, out);
}

// round 6
// speedup vs baseline: 1.3452x; 1.1810x over previous
#include <cuda_runtime.h>
#include <cstdint>

#define N_NODES 100000
#define IN_DIM 128
#define N_HEADS 4
#define D_HEAD 32
#define N_EDGES 800000
#define LN_EPS 1e-5f
#define NEG_SLOPE 0.2f

#define SCAN_BLOCKS 98   // ceil(100000/1024)

// ---- scratch (static device globals; no allocation allowed) ----
__device__ float4 g_h[N_NODES * 32];     // projected features, [N][128] as float4
__device__ float4 g_ssrc[N_NODES];       // per-node src-half score, 4 heads
__device__ float4 g_sdst[N_NODES];       // per-node dst-half score, 4 heads
__device__ int    g_srcs[N_EDGES];       // src ids, CSR-sorted by dst
__device__ int    g_cnt[N_NODES];        // in-degree histogram
__device__ int    g_off[N_NODES];        // CSR row offsets
__device__ int    g_cur[N_NODES];        // scatter cursors
__device__ int    g_bsum[SCAN_BLOCKS];   // scan partials
__device__ int    g_flag;                // scan arrival counter

// ---------------------------------------------------------------
__device__ __forceinline__ uint32_t f2tf(float f) {
    uint32_t u; asm("cvt.rna.tf32.f32 %0, %1;" : "=r"(u) : "f"(f)); return u;
}

__device__ __forceinline__ void mma_tf32(float c[4],
        uint32_t a0, uint32_t a1, uint32_t a2, uint32_t a3,
        uint32_t b0, uint32_t b1)
{
    asm("mma.sync.aligned.m16n8k8.row.col.f32.tf32.tf32.f32 "
        "{%0,%1,%2,%3}, {%4,%5,%6,%7}, {%8,%9}, {%0,%1,%2,%3};"
        : "+f"(c[0]), "+f"(c[1]), "+f"(c[2]), "+f"(c[3])
        : "r"(a0), "r"(a1), "r"(a2), "r"(a3), "r"(b0), "r"(b1));
}

// ---------------------------------------------------------------
// Projection on tensor cores: h = x @ W via mma.m16n8k8 tf32.
// Block: 256 thr, tile 128 rows x 128 cols, K=128.
// Warp w owns rows [blk*128 + w*16, +16). A frags from global (1-step
// prefetch). W staged in smem transposed [n][k] pad-132, tf32.
// Fused epilogue: per-node per-head score halves (h.a_src, h.a_dst).
__global__ void proj_kernel(const float* __restrict__ x, const float* __restrict__ W,
                            const float* __restrict__ a_src, const float* __restrict__ a_dst)
{
    extern __shared__ uint32_t Wt[];   // [128][132] tf32 bits
    int t = threadIdx.x;

    for (int i = t; i < 128 * 128; i += 256) {
        int k = i >> 7, n = i & 127;
        Wt[n * 132 + k] = f2tf(W[i]);
    }
    __syncthreads();

    int lane = t & 31, warp = t >> 5;
    int qr = lane >> 2;          // groupID 0..7
    int lm4 = lane & 3;          // threadID-in-group
    int ra = blockIdx.x * 128 + warp * 16 + qr;
    int rb = ra + 8;
    const float* xa = x + (size_t)((ra < N_NODES) ? ra : N_NODES - 1) * 128 + lm4;
    const float* xb = x + (size_t)((rb < N_NODES) ? rb : N_NODES - 1) * 128 + lm4;

    float c[16][4];
#pragma unroll
    for (int nt = 0; nt < 16; nt++) { c[nt][0] = c[nt][1] = c[nt][2] = c[nt][3] = 0.f; }

    float fa0 = xa[0], fa2 = xa[4], fa1 = xb[0], fa3 = xb[4];

#pragma unroll 1
    for (int ks = 0; ks < 16; ks++) {
        uint32_t a0 = f2tf(fa0), a1 = f2tf(fa1), a2 = f2tf(fa2), a3 = f2tf(fa3);
        if (ks < 15) {
            int kn = ks * 8 + 8;
            fa0 = xa[kn]; fa2 = xa[kn + 4]; fa1 = xb[kn]; fa3 = xb[kn + 4];
        }
        const uint32_t* Wk = Wt + ks * 8 + lm4 + qr * 132;
#pragma unroll
        for (int nt = 0; nt < 16; nt++) {
            uint32_t b0 = Wk[nt * 8 * 132];
            uint32_t b1 = Wk[nt * 8 * 132 + 4];
            mma_tf32(c[nt], a0, a1, a2, a3, b0, b1);
        }
    }

    // ---- epilogue: scores ----
    float asv[4][2], adv[4][2];
#pragma unroll
    for (int q = 0; q < 4; q++) {
#pragma unroll
        for (int jc = 0; jc < 2; jc++) {
            asv[q][jc] = a_src[q * 8 + lm4 * 2 + jc];
            adv[q][jc] = a_dst[q * 8 + lm4 * 2 + jc];
        }
    }
    float psA[4], pdA[4], psB[4], pdB[4];
#pragma unroll
    for (int h = 0; h < 4; h++) { psA[h] = pdA[h] = psB[h] = pdB[h] = 0.f; }
#pragma unroll
    for (int nt = 0; nt < 16; nt++) {
        int h = nt >> 2, q = nt & 3;
        psA[h] += c[nt][0] * asv[q][0] + c[nt][1] * asv[q][1];
        pdA[h] += c[nt][0] * adv[q][0] + c[nt][1] * adv[q][1];
        psB[h] += c[nt][2] * asv[q][0] + c[nt][3] * asv[q][1];
        pdB[h] += c[nt][2] * adv[q][0] + c[nt][3] * adv[q][1];
    }
#pragma unroll
    for (int h = 0; h < 4; h++) {
#pragma unroll
        for (int o = 1; o <= 2; o <<= 1) {
            psA[h] += __shfl_xor_sync(0xffffffffu, psA[h], o);
            pdA[h] += __shfl_xor_sync(0xffffffffu, pdA[h], o);
            psB[h] += __shfl_xor_sync(0xffffffffu, psB[h], o);
            pdB[h] += __shfl_xor_sync(0xffffffffu, pdB[h], o);
        }
    }
    if (lm4 == 0) {
        if (ra < N_NODES) {
            g_ssrc[ra] = make_float4(psA[0], psA[1], psA[2], psA[3]);
            g_sdst[ra] = make_float4(pdA[0], pdA[1], pdA[2], pdA[3]);
        }
        if (rb < N_NODES) {
            g_ssrc[rb] = make_float4(psB[0], psB[1], psB[2], psB[3]);
            g_sdst[rb] = make_float4(pdB[0], pdB[1], pdB[2], pdB[3]);
        }
    }

    // ---- epilogue: write h ----
    float* hf = (float*)g_h;
    if (ra < N_NODES) {
        float* p = hf + (size_t)ra * 128 + lm4 * 2;
#pragma unroll
        for (int nt = 0; nt < 16; nt++)
            *(float2*)(p + nt * 8) = make_float2(c[nt][0], c[nt][1]);
    }
    if (rb < N_NODES) {
        float* p = hf + (size_t)rb * 128 + lm4 * 2;
#pragma unroll
        for (int nt = 0; nt < 16; nt++)
            *(float2*)(p + nt * 8) = make_float2(c[nt][2], c[nt][3]);
    }
}

// ---------------------------------------------------------------
// Histogram of dst (int4-vectorized); resets the scan flag.
__global__ void hist_kernel(const int4* __restrict__ dst4) {
    if (blockIdx.x == 0 && threadIdx.x == 0) g_flag = 0;
    int i = blockIdx.x * blockDim.x + threadIdx.x;
    if (i >= N_EDGES / 4) return;
    int4 d = dst4[i];
    atomicAdd(&g_cnt[d.x], 1);
    atomicAdd(&g_cnt[d.y], 1);
    atomicAdd(&g_cnt[d.z], 1);
    atomicAdd(&g_cnt[d.w], 1);
}

// ---------------------------------------------------------------
__device__ __forceinline__ int block_scan_inclusive(int v, int t, int* total) {
    __shared__ int wsum[32];
    int lane = t & 31, wid = t >> 5;
    int x = v;
#pragma unroll
    for (int o = 1; o < 32; o <<= 1) {
        int y = __shfl_up_sync(0xffffffffu, x, o);
        if (lane >= o) x += y;
    }
    if (lane == 31) wsum[wid] = x;
    __syncthreads();
    int nw = blockDim.x >> 5;
    if (t < 32) {
        int s = (t < nw) ? wsum[t] : 0;
#pragma unroll
        for (int o = 1; o < 32; o <<= 1) {
            int y = __shfl_up_sync(0xffffffffu, s, o);
            if (t >= o) s += y;
        }
        wsum[t] = s;
    }
    __syncthreads();
    int pre = (wid > 0) ? wsum[wid - 1] : 0;
    *total = wsum[nw - 1];
    return x + pre;
}

// Single-wave fused scan (98 blocks < 148 SMs, co-resident).
__global__ void scan_all_kernel() {
    __shared__ int sb[SCAN_BLOCKS];
    int b = blockIdx.x, t = threadIdx.x;
    int i = b * 1024 + t;
    int v = (i < N_NODES) ? g_cnt[i] : 0;
    int total;
    int incl = block_scan_inclusive(v, t, &total);
    if (t == 0) {
        g_bsum[b] = total;
        __threadfence();
        atomicAdd(&g_flag, 1);
        while (((volatile int*)&g_flag)[0] < SCAN_BLOCKS) { }
    }
    __syncthreads();
    if (t < SCAN_BLOCKS) sb[t] = ((volatile int*)g_bsum)[t];
    __syncthreads();
    int pre = 0;
    for (int j = 0; j < b; j++) pre += sb[j];
    if (i < N_NODES) {
        int o = pre + incl - v;
        g_off[i] = o;
        g_cur[i] = o;
    }
}

// ---------------------------------------------------------------
// Scatter ONLY the src id into the dst-grouped CSR (int4-vectorized).
__global__ void scatter_kernel(const int4* __restrict__ src4, const int4* __restrict__ dst4) {
    int i = blockIdx.x * blockDim.x + threadIdx.x;
    if (i >= N_EDGES / 4) return;
    int4 s = src4[i];
    int4 d = dst4[i];
    int p0 = atomicAdd(&g_cur[d.x], 1); g_srcs[p0] = s.x;
    int p1 = atomicAdd(&g_cur[d.y], 1); g_srcs[p1] = s.y;
    int p2 = atomicAdd(&g_cur[d.z], 1); g_srcs[p2] = s.z;
    int p3 = atomicAdd(&g_cur[d.w], 1); g_srcs[p3] = s.w;
}

// ---------------------------------------------------------------
__device__ __forceinline__ float expleaky(float v) {
    v = (v > 0.f) ? v : NEG_SLOPE * v;
    return __expf(v);
}

// Warp per dst node: recompute scores, softmax-weighted aggregation,
// residual + LN + ELU. Src ids loaded coalesced (32/load) + shuffled.
__global__ void agg_kernel(const float* __restrict__ x,
                           const float* __restrict__ gamma, const float* __restrict__ beta,
                           float* __restrict__ out)
{
    int w = (blockIdx.x * blockDim.x + threadIdx.x) >> 5;
    int lane = threadIdx.x & 31;
    if (w >= N_NODES) return;

    int start = g_off[w];
    int deg = g_cnt[w];
    int head = lane >> 3;

    const float* ssrc_f = (const float*)g_ssrc;
    float sdst_h = ((const float*)g_sdst)[w * 4 + head];

    float4 acc = make_float4(0.f, 0.f, 0.f, 0.f);
    float dsum = 0.f;

    for (int chunk = 0; chunk < deg; chunk += 32) {
        int n = deg - chunk; if (n > 32) n = 32;
        int myid = 0;
        if (lane < n) myid = g_srcs[start + chunk + lane];   // coalesced

        int i = 0;
#pragma unroll 1
        for (; i + 4 <= n; i += 4) {
            int s0 = __shfl_sync(0xffffffffu, myid, i);
            int s1 = __shfl_sync(0xffffffffu, myid, i + 1);
            int s2 = __shfl_sync(0xffffffffu, myid, i + 2);
            int s3 = __shfl_sync(0xffffffffu, myid, i + 3);
            float4 h0 = g_h[s0 * 32 + lane];
            float4 h1 = g_h[s1 * 32 + lane];
            float4 h2 = g_h[s2 * 32 + lane];
            float4 h3 = g_h[s3 * 32 + lane];
            float w0 = expleaky(ssrc_f[s0 * 4 + head] + sdst_h);
            float w1 = expleaky(ssrc_f[s1 * 4 + head] + sdst_h);
            float w2 = expleaky(ssrc_f[s2 * 4 + head] + sdst_h);
            float w3 = expleaky(ssrc_f[s3 * 4 + head] + sdst_h);
            acc.x += h0.x * w0 + h1.x * w1 + h2.x * w2 + h3.x * w3;
            acc.y += h0.y * w0 + h1.y * w1 + h2.y * w2 + h3.y * w3;
            acc.z += h0.z * w0 + h1.z * w1 + h2.z * w2 + h3.z * w3;
            acc.w += h0.w * w0 + h1.w * w1 + h2.w * w2 + h3.w * w3;
            dsum += w0 + w1 + w2 + w3;
        }
#pragma unroll 1
        for (; i < n; i++) {
            int s0 = __shfl_sync(0xffffffffu, myid, i);
            float4 h0 = g_h[s0 * 32 + lane];
            float w0 = expleaky(ssrc_f[s0 * 4 + head] + sdst_h);
            acc.x += h0.x * w0; acc.y += h0.y * w0; acc.z += h0.z * w0; acc.w += h0.w * w0;
            dsum += w0;
        }
    }
    float inv = (deg > 0) ? (1.f / dsum) : 0.f;

    const float4* x4 = (const float4*)x;
    float4 xv = x4[w * 32 + lane];
    float r0 = acc.x * inv + xv.x;
    float r1 = acc.y * inv + xv.y;
    float r2 = acc.z * inv + xv.z;
    float r3 = acc.w * inv + xv.w;

    // LayerNorm over 128 (32 lanes x 4)
    float s1 = r0 + r1 + r2 + r3;
#pragma unroll
    for (int o = 16; o; o >>= 1) s1 += __shfl_xor_sync(0xffffffffu, s1, o);
    float mean = s1 * (1.0f / 128.0f);
    float d0 = r0 - mean, d1 = r1 - mean, d2 = r2 - mean, d3 = r3 - mean;
    float s2 = d0 * d0 + d1 * d1 + d2 * d2 + d3 * d3;
#pragma unroll
    for (int o = 16; o; o >>= 1) s2 += __shfl_xor_sync(0xffffffffu, s2, o);
    float rstd = rsqrtf(s2 * (1.0f / 128.0f) + LN_EPS);

    float4 g = ((const float4*)gamma)[lane];
    float4 bb = ((const float4*)beta)[lane];
    float o0 = d0 * rstd * g.x + bb.x;
    float o1 = d1 * rstd * g.y + bb.y;
    float o2 = d2 * rstd * g.z + bb.z;
    float o3 = d3 * rstd * g.w + bb.w;
    o0 = (o0 > 0.f) ? o0 : expm1f(o0);
    o1 = (o1 > 0.f) ? o1 : expm1f(o1);
    o2 = (o2 > 0.f) ? o2 : expm1f(o2);
    o3 = (o3 > 0.f) ? o3 : expm1f(o3);

    ((float4*)out)[w * 32 + lane] = make_float4(o0, o1, o2, o3);
}

// ---------------------------------------------------------------
extern "C" void kernel_launch(void* const* d_in, const int* in_sizes, int n_in,
                              void* d_out, int out_size)
{
    const float* x      = (const float*)d_in[0];
    const int*   ei     = (const int*)d_in[1];
    const float* W      = (const float*)d_in[2];
    const float* a_src  = (const float*)d_in[3];
    const float* a_dst  = (const float*)d_in[4];
    const float* gamma  = (const float*)d_in[5];
    const float* beta   = (const float*)d_in[6];
    float* out = (float*)d_out;

    const int4* src4 = (const int4*)ei;
    const int4* dst4 = (const int4*)(ei + N_EDGES);

    const int PROJ_SMEM = 128 * 132 * 4;   // 67584 B
    cudaFuncSetAttribute(proj_kernel, cudaFuncAttributeMaxDynamicSharedMemorySize, PROJ_SMEM);

    void* cnt_addr = nullptr;
    cudaGetSymbolAddress(&cnt_addr, g_cnt);
    cudaMemsetAsync(cnt_addr, 0, N_NODES * sizeof(int), 0);

    hist_kernel<<<(N_EDGES / 4 + 255) / 256, 256>>>(dst4);
    scan_all_kernel<<<SCAN_BLOCKS, 1024>>>();
    scatter_kernel<<<(N_EDGES / 4 + 255) / 256, 256>>>(src4, dst4);
    proj_kernel<<<(N_NODES + 127) / 128, 256, PROJ_SMEM>>>(x, W, a_src, a_dst);
    agg_kernel<<<(N_NODES * 32 + 255) / 256, 256>>>(x, gamma, beta, out);
}